// round 2
// baseline (speedup 1.0000x reference)
#include <cuda_runtime.h>
#include <math_constants.h>

// Sparsemax (dim=2) over x[8,1024,2048]: per row of length K=2048:
//   right = cumsum(z); mask = (1 + (k+1)*z_k) <= right_k
//   kmax = max (k+1) over !mask ; tmax = max right over !mask
//   tau = (tmax-1)/kmax ; out = relu(z - tau)
//
// One CTA per row. 256 threads x 8 elems/thread (2x float4). Single pass,
// exactly one HBM read + one write per element. Only 2 __syncthreads():
// cross-warp scan offsets and the (kmax,tmax) reduction are both done
// redundantly per-thread over the 8 warp partials in shared memory.

#define ROW_LEN 2048
#define THREADS 256
#define NWARP (THREADS / 32)
#define EPT 8  // elements per thread

__global__ __launch_bounds__(THREADS, 8)
void sparsemax_kernel(const float* __restrict__ x, float* __restrict__ out) {
    const long long row = blockIdx.x;
    const float* __restrict__ xr = x + row * (long long)ROW_LEN;
    float* __restrict__ orow = out + row * (long long)ROW_LEN;

    const int tid = threadIdx.x;
    const int lane = tid & 31;
    const int warp = tid >> 5;

    // ---- load 8 contiguous floats (two float4) into registers ----
    float v[EPT];
    {
        const float4 a = __ldg((const float4*)(xr + tid * EPT));
        const float4 b = __ldg((const float4*)(xr + tid * EPT + 4));
        v[0] = a.x; v[1] = a.y; v[2] = a.z; v[3] = a.w;
        v[4] = b.x; v[5] = b.y; v[6] = b.z; v[7] = b.w;
    }

    // ---- local inclusive prefix sums ----
    float p[EPT];
    float run = 0.f;
#pragma unroll
    for (int j = 0; j < EPT; ++j) { run += v[j]; p[j] = run; }
    const float local_sum = run;

    // ---- warp-inclusive scan of per-thread sums ----
    float s = local_sum;
#pragma unroll
    for (int o = 1; o < 32; o <<= 1) {
        float t = __shfl_up_sync(0xFFFFFFFFu, s, o);
        if (lane >= o) s += t;
    }

    __shared__ float wsum[NWARP];
    if (lane == 31) wsum[warp] = s;
    __syncthreads();

    // exclusive offset for this thread: sum of preceding warps (redundant
    // per-thread, only NWARP-1 adds) + warp-exclusive part
    float excl = s - local_sum;
#pragma unroll
    for (int w = 0; w < NWARP - 1; ++w)
        if (w < warp) excl += wsum[w];

    // ---- masked maxes ----
    float kmax = 0.f;            // max (k+1) where mask false
    float tmax = -CUDART_INF_F;  // max cumsum where mask false
    const float kbase = (float)(tid * EPT);
#pragma unroll
    for (int j = 0; j < EPT; ++j) {
        const float right = excl + p[j];
        const float kf = kbase + (float)(j + 1);
        const float left = fmaf(kf, v[j], 1.0f);
        if (!(left <= right)) {
            kmax = fmaxf(kmax, kf);
            tmax = fmaxf(tmax, right);
        }
    }

    // ---- warp max-reduce, then redundant per-thread block reduce ----
#pragma unroll
    for (int o = 16; o > 0; o >>= 1) {
        kmax = fmaxf(kmax, __shfl_xor_sync(0xFFFFFFFFu, kmax, o));
        tmax = fmaxf(tmax, __shfl_xor_sync(0xFFFFFFFFu, tmax, o));
    }
    __shared__ float skm[NWARP], stm[NWARP];
    if (lane == 0) { skm[warp] = kmax; stm[warp] = tmax; }
    __syncthreads();

    float K = skm[0], T = stm[0];
#pragma unroll
    for (int i = 1; i < NWARP; ++i) {
        K = fmaxf(K, skm[i]);
        T = fmaxf(T, stm[i]);
    }
    const float tau = (T - 1.0f) / K;

    // ---- write relu(v - tau) ----
    float4 oa, ob;
    oa.x = fmaxf(v[0] - tau, 0.f); oa.y = fmaxf(v[1] - tau, 0.f);
    oa.z = fmaxf(v[2] - tau, 0.f); oa.w = fmaxf(v[3] - tau, 0.f);
    ob.x = fmaxf(v[4] - tau, 0.f); ob.y = fmaxf(v[5] - tau, 0.f);
    ob.z = fmaxf(v[6] - tau, 0.f); ob.w = fmaxf(v[7] - tau, 0.f);
    *(float4*)(orow + tid * EPT) = oa;
    *(float4*)(orow + tid * EPT + 4) = ob;
}

extern "C" void kernel_launch(void* const* d_in, const int* in_sizes, int n_in,
                              void* d_out, int out_size) {
    const float* x = (const float*)d_in[0];
    float* out = (float*)d_out;
    const int n = in_sizes[0];            // 8*1024*2048
    const int rows = n / ROW_LEN;         // 8192
    sparsemax_kernel<<<rows, THREADS>>>(x, out);
}

// round 8
// speedup vs baseline: 1.3729x; 1.3729x over previous
#include <cuda_runtime.h>
#include <math_constants.h>

// Sparsemax (dim=2) over x[8,1024,2048]. Per row of length K=2048:
//   right = cumsum(z); mask = (1 + (k+1)*z_k) <= right_k
//   kmax = max (k+1) over !mask ; tmax = max right over !mask
//   tau = (tmax-1)/kmax ; out = relu(z - tau)
//
// One CTA per row. 128 threads x 16 elems/thread (4x float4). Single pass.
// MIO-minimized: 5 SHFL (scan) + 2 REDUX (maxes) per thread, 2 barriers.

#define ROW_LEN 2048
#define THREADS 128
#define NWARP (THREADS / 32)
#define EPT 16  // elements per thread

__global__ __launch_bounds__(THREADS, 8)
void sparsemax_kernel(const float* __restrict__ x, float* __restrict__ out) {
    const long long row = blockIdx.x;
    const float* __restrict__ xr = x + row * (long long)ROW_LEN;
    float* __restrict__ orow = out + row * (long long)ROW_LEN;

    const int tid = threadIdx.x;
    const int lane = tid & 31;
    const int warp = tid >> 5;

    // ---- load 16 contiguous floats (4x float4), streaming ----
    float v[EPT];
    {
        const float4* src = (const float4*)(xr + tid * EPT);
        float4 q0 = __ldcs(src + 0);
        float4 q1 = __ldcs(src + 1);
        float4 q2 = __ldcs(src + 2);
        float4 q3 = __ldcs(src + 3);
        v[0] = q0.x;  v[1] = q0.y;  v[2] = q0.z;  v[3] = q0.w;
        v[4] = q1.x;  v[5] = q1.y;  v[6] = q1.z;  v[7] = q1.w;
        v[8] = q2.x;  v[9] = q2.y;  v[10] = q2.z; v[11] = q2.w;
        v[12] = q3.x; v[13] = q3.y; v[14] = q3.z; v[15] = q3.w;
    }

    // ---- local sum (prefix regenerated later; keeps regs low) ----
    float local_sum = 0.f;
#pragma unroll
    for (int j = 0; j < EPT; ++j) local_sum += v[j];

    // ---- warp-inclusive scan of per-thread sums (5 SHFL) ----
    float s = local_sum;
#pragma unroll
    for (int o = 1; o < 32; o <<= 1) {
        float t = __shfl_up_sync(0xFFFFFFFFu, s, o);
        if (lane >= o) s += t;
    }

    __shared__ float wsum[NWARP];
    if (lane == 31) wsum[warp] = s;
    __syncthreads();

    // exclusive offset: warp-exclusive part + sum of preceding warp totals
    float excl = s - local_sum;
#pragma unroll
    for (int w = 0; w < NWARP - 1; ++w)
        if (w < warp) excl += wsum[w];

    // ---- masked maxes (cumsum regenerated incrementally from excl) ----
    float kmax = 0.f;            // max (k+1) where mask false; >= 1 overall
    float tmax = -CUDART_INF_F;  // max cumsum where mask false
    const float kbase = (float)(tid * EPT);
    float right = excl;
#pragma unroll
    for (int j = 0; j < EPT; ++j) {
        right += v[j];
        const float kf = kbase + (float)(j + 1);
        const float left = fmaf(kf, v[j], 1.0f);
        if (!(left <= right)) {
            kmax = fmaxf(kmax, kf);
            tmax = fmaxf(tmax, right);
        }
    }

    // ---- warp max-reduce via REDUX on order-preserving uint keys ----
    // kmax >= 0 -> raw IEEE bits are monotone under uint compare.
    unsigned ku = __reduce_max_sync(0xFFFFFFFFu, __float_as_uint(kmax));
    // tmax may be negative / -inf: sign-flip map (monotone total order).
    unsigned tb = __float_as_uint(tmax);
    unsigned tkey = ((int)tb >= 0) ? (tb | 0x80000000u) : ~tb;
    unsigned tu = __reduce_max_sync(0xFFFFFFFFu, tkey);

    __shared__ unsigned skm[NWARP], stm[NWARP];
    if (lane == 0) { skm[warp] = ku; stm[warp] = tu; }
    __syncthreads();

    unsigned Ku = skm[0], Tu = stm[0];
#pragma unroll
    for (int i = 1; i < NWARP; ++i) {
        Ku = max(Ku, skm[i]);
        Tu = max(Tu, stm[i]);
    }
    const float K = __uint_as_float(Ku);
    const float T = __uint_as_float((Tu & 0x80000000u) ? (Tu & 0x7FFFFFFFu) : ~Tu);
    const float tau = (T - 1.0f) / K;

    // ---- write relu(v - tau), streaming ----
    float4* dst = (float4*)(orow + tid * EPT);
    float4 o0, o1, o2, o3;
    o0.x = fmaxf(v[0] - tau, 0.f);  o0.y = fmaxf(v[1] - tau, 0.f);
    o0.z = fmaxf(v[2] - tau, 0.f);  o0.w = fmaxf(v[3] - tau, 0.f);
    o1.x = fmaxf(v[4] - tau, 0.f);  o1.y = fmaxf(v[5] - tau, 0.f);
    o1.z = fmaxf(v[6] - tau, 0.f);  o1.w = fmaxf(v[7] - tau, 0.f);
    o2.x = fmaxf(v[8] - tau, 0.f);  o2.y = fmaxf(v[9] - tau, 0.f);
    o2.z = fmaxf(v[10] - tau, 0.f); o2.w = fmaxf(v[11] - tau, 0.f);
    o3.x = fmaxf(v[12] - tau, 0.f); o3.y = fmaxf(v[13] - tau, 0.f);
    o3.z = fmaxf(v[14] - tau, 0.f); o3.w = fmaxf(v[15] - tau, 0.f);
    __stcs(dst + 0, o0);
    __stcs(dst + 1, o1);
    __stcs(dst + 2, o2);
    __stcs(dst + 3, o3);
}

extern "C" void kernel_launch(void* const* d_in, const int* in_sizes, int n_in,
                              void* d_out, int out_size) {
    const float* x = (const float*)d_in[0];
    float* out = (float*)d_out;
    const int n = in_sizes[0];            // 8*1024*2048
    const int rows = n / ROW_LEN;         // 8192
    sparsemax_kernel<<<rows, THREADS>>>(x, out);
}

// round 14
// speedup vs baseline: 1.4716x; 1.0719x over previous
#include <cuda_runtime.h>
#include <math_constants.h>

// Sparsemax (dim=2) over x[8,1024,2048]. Per row of length K=2048:
//   right = cumsum(z); mask = (1 + (k+1)*z_k) <= right_k
//   kmax = max (k+1) over !mask ; tmax = max right over !mask
//   tau = (tmax-1)/kmax ; out = relu(z - tau)
//
// One CTA per row. 256 threads x 8 elems/thread (2x float4). Single pass.
// MIO-light: 5 SHFL (scan) + 2 REDUX (maxes) per thread, 2 barriers.
// 8 warps/CTA for latency hiding (R8 showed EPT=16/4-warp was latency-bound).

#define ROW_LEN 2048
#define THREADS 256
#define NWARP (THREADS / 32)
#define EPT 8  // elements per thread

__global__ __launch_bounds__(THREADS, 8)
void sparsemax_kernel(const float* __restrict__ x, float* __restrict__ out) {
    const long long row = blockIdx.x;
    const float* __restrict__ xr = x + row * (long long)ROW_LEN;
    float* __restrict__ orow = out + row * (long long)ROW_LEN;

    const int tid = threadIdx.x;
    const int lane = tid & 31;
    const int warp = tid >> 5;

    // ---- load 8 contiguous floats (2x float4), streaming ----
    float v[EPT];
    {
        const float4* src = (const float4*)(xr + tid * EPT);
        float4 q0 = __ldcs(src + 0);
        float4 q1 = __ldcs(src + 1);
        v[0] = q0.x; v[1] = q0.y; v[2] = q0.z; v[3] = q0.w;
        v[4] = q1.x; v[5] = q1.y; v[6] = q1.z; v[7] = q1.w;
    }

    // ---- local sum ----
    float local_sum = 0.f;
#pragma unroll
    for (int j = 0; j < EPT; ++j) local_sum += v[j];

    // ---- warp-inclusive scan of per-thread sums (5 SHFL) ----
    float s = local_sum;
#pragma unroll
    for (int o = 1; o < 32; o <<= 1) {
        float t = __shfl_up_sync(0xFFFFFFFFu, s, o);
        if (lane >= o) s += t;
    }

    __shared__ float wsum[NWARP];
    if (lane == 31) wsum[warp] = s;
    __syncthreads();

    // exclusive offset: warp-exclusive part + sum of preceding warp totals
    float excl = s - local_sum;
#pragma unroll
    for (int w = 0; w < NWARP - 1; ++w)
        if (w < warp) excl += wsum[w];

    // ---- masked maxes (cumsum regenerated incrementally from excl) ----
    float kmax = 0.f;            // max (k+1) where mask false; >= 1 overall
    float tmax = -CUDART_INF_F;  // max cumsum where mask false
    const float kbase = (float)(tid * EPT);
    float right = excl;
#pragma unroll
    for (int j = 0; j < EPT; ++j) {
        right += v[j];
        const float kf = kbase + (float)(j + 1);
        const float left = fmaf(kf, v[j], 1.0f);
        if (!(left <= right)) {
            kmax = fmaxf(kmax, kf);
            tmax = fmaxf(tmax, right);
        }
    }

    // ---- warp max-reduce via REDUX on order-preserving uint keys ----
    // kmax >= 0 -> raw IEEE bits are monotone under uint compare.
    unsigned ku = __reduce_max_sync(0xFFFFFFFFu, __float_as_uint(kmax));
    // tmax may be negative / -inf: sign-flip map (monotone total order).
    unsigned tb = __float_as_uint(tmax);
    unsigned tkey = ((int)tb >= 0) ? (tb | 0x80000000u) : ~tb;
    unsigned tu = __reduce_max_sync(0xFFFFFFFFu, tkey);

    __shared__ unsigned skm[NWARP], stm[NWARP];
    if (lane == 0) { skm[warp] = ku; stm[warp] = tu; }
    __syncthreads();

    unsigned Ku = skm[0], Tu = stm[0];
#pragma unroll
    for (int i = 1; i < NWARP; ++i) {
        Ku = max(Ku, skm[i]);
        Tu = max(Tu, stm[i]);
    }
    const float K = __uint_as_float(Ku);
    const float T = __uint_as_float((Tu & 0x80000000u) ? (Tu & 0x7FFFFFFFu) : ~Tu);
    const float tau = (T - 1.0f) / K;

    // ---- write relu(v - tau), streaming ----
    float4* dst = (float4*)(orow + tid * EPT);
    float4 o0, o1;
    o0.x = fmaxf(v[0] - tau, 0.f); o0.y = fmaxf(v[1] - tau, 0.f);
    o0.z = fmaxf(v[2] - tau, 0.f); o0.w = fmaxf(v[3] - tau, 0.f);
    o1.x = fmaxf(v[4] - tau, 0.f); o1.y = fmaxf(v[5] - tau, 0.f);
    o1.z = fmaxf(v[6] - tau, 0.f); o1.w = fmaxf(v[7] - tau, 0.f);
    __stcs(dst + 0, o0);
    __stcs(dst + 1, o1);
}

extern "C" void kernel_launch(void* const* d_in, const int* in_sizes, int n_in,
                              void* d_out, int out_size) {
    const float* x = (const float*)d_in[0];
    float* out = (float*)d_out;
    const int n = in_sizes[0];            // 8*1024*2048
    const int rows = n / ROW_LEN;         // 8192
    sparsemax_kernel<<<rows, THREADS>>>(x, out);
}